// round 3
// baseline (speedup 1.0000x reference)
#include <cuda_runtime.h>

#define NN 50000
#define IN_FT 256
#define OUT_FT 64
#define NE 800000

// Scratch for fc(seq): [N, 64] fp32 = 12.8 MB.
__device__ float g_fts[NN * OUT_FT];

// ---- f32x2 helpers (packed dual-FMA; ptxas never auto-fuses this) ----------
__device__ __forceinline__ unsigned long long pack2(float x, float y) {
    unsigned long long r;
    asm("mov.b64 %0, {%1, %2};" : "=l"(r) : "f"(x), "f"(y));
    return r;
}
__device__ __forceinline__ void unpack2(unsigned long long v, float& x, float& y) {
    asm("mov.b64 {%0, %1}, %2;" : "=f"(x), "=f"(y) : "l"(v));
}
__device__ __forceinline__ void ffma2(unsigned long long& d,
                                      unsigned long long a, unsigned long long b) {
    asm("fma.rn.f32x2 %0, %1, %2, %3;" : "=l"(d) : "l"(a), "l"(b), "l"(d));
}

// ---------------------------------------------------------------------------
// GEMM: fts[n][o] = sum_k seq[n][k] * W[o][k], fused out[row][:] = bias[:].
// BM=128, BN=64, BK=16, 256 threads. Thread tile 4 rows x 8 cols as
// 4x4 f32x2 accumulators. B loads are broadcast-heavy LDS.128 (cheap on
// crossbar); A loads are conflict-free scalar LDS (stride 17 pad).
// ---------------------------------------------------------------------------
#define SA_STRIDE 17
#define SB_STRIDE 68

__global__ __launch_bounds__(256) void gemm_kernel(
    const float* __restrict__ seq, const float* __restrict__ W,
    const float* __restrict__ bias,
    float* __restrict__ fts, float* __restrict__ out)
{
    __shared__ float sA[128 * SA_STRIDE];                 // [row][k], 8.5 KB
    __shared__ __align__(16) float sB[16 * SB_STRIDE];    // [k][col], 4.25 KB

    const int t    = threadIdx.x;
    const int tx   = t & 7;          // col group: cols tx*8 .. tx*8+7
    const int ty   = t >> 3;         // row group: rows ty*4 .. ty*4+3
    const int row0 = blockIdx.x * 128;

    // Fused init: out[row][:] = bias[:] for this block's rows (un-poisons d_out).
    {
        const float4* b4 = (const float4*)bias;
        for (int i = t; i < 128 * 16; i += 256) {
            int r  = i >> 4;
            int cq = i & 15;
            if (row0 + r < NN)
                *(float4*)&out[(size_t)(row0 + r) * OUT_FT + cq * 4] = b4[cq];
        }
    }

    unsigned long long acc[4][4];
#pragma unroll
    for (int r = 0; r < 4; r++)
#pragma unroll
        for (int c = 0; c < 4; c++) acc[r][c] = 0ull;

    for (int kt = 0; kt < IN_FT; kt += 16) {
        // Load seq tile: 128 rows x 16 k = 512 float4, 2 per thread.
#pragma unroll
        for (int i = 0; i < 2; i++) {
            int idx = t + i * 256;          // 0..511
            int r   = idx >> 2;             // row 0..127
            int kq  = idx & 3;              // float4 slot in k (0..3)
            float4 v = make_float4(0.f, 0.f, 0.f, 0.f);
            if (row0 + r < NN)
                v = *(const float4*)&seq[(size_t)(row0 + r) * IN_FT + kt + kq * 4];
            float* p = &sA[r * SA_STRIDE + kq * 4];
            p[0] = v.x; p[1] = v.y; p[2] = v.z; p[3] = v.w;
        }
        // Load W tile transposed: W[o][kt+..] -> sB[k][o]. 256 float4, 1/thread.
        {
            int o  = t >> 2;                // 0..63
            int kq = t & 3;                 // 0..3
            float4 v = *(const float4*)&W[o * IN_FT + kt + kq * 4];
            sB[(kq * 4 + 0) * SB_STRIDE + o] = v.x;
            sB[(kq * 4 + 1) * SB_STRIDE + o] = v.y;
            sB[(kq * 4 + 2) * SB_STRIDE + o] = v.z;
            sB[(kq * 4 + 3) * SB_STRIDE + o] = v.w;
        }
        __syncthreads();

#pragma unroll
        for (int kk = 0; kk < 16; kk++) {
            // 8 B columns for this k as 4 f32x2 pairs (two LDS.128).
            const float* bp = &sB[kk * SB_STRIDE + tx * 8];
            float4 blo = *(const float4*)bp;        // cols 0..3
            float4 bhi = *(const float4*)(bp + 4);  // cols 4..7
            unsigned long long b0 = pack2(blo.x, blo.y);
            unsigned long long b1 = pack2(blo.z, blo.w);
            unsigned long long b2 = pack2(bhi.x, bhi.y);
            unsigned long long b3 = pack2(bhi.z, bhi.w);

#pragma unroll
            for (int r = 0; r < 4; r++) {
                float a = sA[(ty * 4 + r) * SA_STRIDE + kk];
                unsigned long long aa = pack2(a, a);
                ffma2(acc[r][0], aa, b0);
                ffma2(acc[r][1], aa, b1);
                ffma2(acc[r][2], aa, b2);
                ffma2(acc[r][3], aa, b3);
            }
        }
        __syncthreads();
    }

#pragma unroll
    for (int r = 0; r < 4; r++) {
        int row = row0 + ty * 4 + r;
        if (row < NN) {
            float4 v0, v1;
            unpack2(acc[r][0], v0.x, v0.y);
            unpack2(acc[r][1], v0.z, v0.w);
            unpack2(acc[r][2], v1.x, v1.y);
            unpack2(acc[r][3], v1.z, v1.w);
            float* p = &fts[(size_t)row * OUT_FT + tx * 8];
            *(float4*)p       = v0;
            *(float4*)(p + 4) = v1;
        }
    }
}

// ---------------------------------------------------------------------------
// Scatter: out[dst] += fts[src] * val, 16 threads/edge, RED.v4 (no return).
// ---------------------------------------------------------------------------
__global__ __launch_bounds__(256) void scatter_kernel(
    const float* __restrict__ fts,
    const int* __restrict__ esrc, const int* __restrict__ edst,
    const float* __restrict__ eval, float* __restrict__ out)
{
    long long gid = (long long)blockIdx.x * blockDim.x + threadIdx.x;
    int e    = (int)(gid >> 4);
    int part = (int)(gid & 15);
    if (e >= NE) return;

    int   s = __ldg(&esrc[e]);
    int   d = __ldg(&edst[e]);
    float v = __ldg(&eval[e]);

    float4 f = *(const float4*)&fts[(size_t)s * OUT_FT + part * 4];
    float* p = &out[(size_t)d * OUT_FT + part * 4];
    asm volatile("red.global.add.v4.f32 [%0], {%1, %2, %3, %4};"
                 :: "l"(p), "f"(f.x * v), "f"(f.y * v), "f"(f.z * v), "f"(f.w * v)
                 : "memory");
}

// ---------------------------------------------------------------------------
// PReLU (scalar alpha), float4-vectorized, in place.
// ---------------------------------------------------------------------------
__global__ __launch_bounds__(256) void prelu_kernel(
    float4* __restrict__ out, const float* __restrict__ alpha)
{
    int i = blockIdx.x * blockDim.x + threadIdx.x;
    if (i < NN * OUT_FT / 4) {
        float a = __ldg(&alpha[0]);
        float4 x = out[i];
        x.x = (x.x >= 0.0f) ? x.x : a * x.x;
        x.y = (x.y >= 0.0f) ? x.y : a * x.y;
        x.z = (x.z >= 0.0f) ? x.z : a * x.z;
        x.w = (x.w >= 0.0f) ? x.w : a * x.w;
        out[i] = x;
    }
}

extern "C" void kernel_launch(void* const* d_in, const int* in_sizes, int n_in,
                              void* d_out, int out_size)
{
    const float* seq   = (const float*)d_in[0];
    const float* W     = (const float*)d_in[1];
    const float* bias  = (const float*)d_in[2];
    const float* alpha = (const float*)d_in[3];
    const int*   esrc  = (const int*)d_in[4];
    const int*   edst  = (const int*)d_in[5];
    const float* eval  = (const float*)d_in[6];
    float* out = (float*)d_out;

    float* fts;
    cudaGetSymbolAddress((void**)&fts, g_fts);

    // 1) GEMM (FFMA2, broadcast-tiled) + fused out = bias
    gemm_kernel<<<(NN + 127) / 128, 256>>>(seq, W, bias, fts, out);

    // 2) scatter-add over edges
    long long total = (long long)NE * 16;
    scatter_kernel<<<(unsigned)((total + 255) / 256), 256>>>(fts, esrc, edst, eval, out);

    // 3) PReLU in place (vectorized)
    prelu_kernel<<<(NN * OUT_FT / 4 + 255) / 256, 256>>>((float4*)out, alpha);
}

// round 5
// speedup vs baseline: 1.2702x; 1.2702x over previous
#include <cuda_runtime.h>
#include <cstdint>

#define NN 50000
#define IN_FT 256
#define OUT_FT 64
#define NE 800000

// Scratch for fc(seq): [N, 64] fp32 = 12.8 MB.
__device__ float g_fts[NN * OUT_FT];

// ---- f32x2 helpers (packed dual-FMA; ptxas never auto-fuses this) ----------
__device__ __forceinline__ unsigned long long pack2(float x, float y) {
    unsigned long long r;
    asm("mov.b64 %0, {%1, %2};" : "=l"(r) : "f"(x), "f"(y));
    return r;
}
__device__ __forceinline__ void unpack2(unsigned long long v, float& x, float& y) {
    asm("mov.b64 {%0, %1}, %2;" : "=f"(x), "=f"(y) : "l"(v));
}
__device__ __forceinline__ void ffma2(unsigned long long& d,
                                      unsigned long long a, unsigned long long b) {
    asm("fma.rn.f32x2 %0, %1, %2, %3;" : "=l"(d) : "l"(a), "l"(b), "l"(d));
}

// ---------------------------------------------------------------------------
// GEMM: fts[n][o] = sum_k seq[n][k] * W[o][k], fused out[row][:] = bias[:].
// 128 threads, BM=128, BN=64, BK=16. Thread tile 8 rows x 8 cols as 8x4
// f32x2 accumulators. Shared-byte economy: 0.625 B/FMA (A reads are 8-way
// broadcast: only 4 distinct addresses per warp; B reads 4-way broadcast).
// ---------------------------------------------------------------------------
#define GT 128           // threads per gemm block
#define SA_STRIDE 17
#define SB_STRIDE 68

__global__ __launch_bounds__(GT) void gemm_kernel(
    const float* __restrict__ seq, const float* __restrict__ W,
    const float* __restrict__ bias,
    float* __restrict__ fts, float* __restrict__ out)
{
    __shared__ float sA[128 * SA_STRIDE];                 // [row][k], 8.5 KB
    __shared__ __align__(16) float sB[16 * SB_STRIDE];    // [k][col], 4.25 KB

    const int t    = threadIdx.x;
    const int tx   = t & 7;          // col group: cols tx*8 .. tx*8+7
    const int ty   = t >> 3;         // row group: rows ty*8 .. ty*8+7 (0..15)
    const int row0 = blockIdx.x * 128;

    // Fused init: out[row][:] = bias[:] for this block's rows (un-poisons d_out).
    {
        const float4* b4 = (const float4*)bias;
        for (int i = t; i < 128 * 16; i += GT) {
            int r  = i >> 4;
            int cq = i & 15;
            if (row0 + r < NN)
                *(float4*)&out[(size_t)(row0 + r) * OUT_FT + cq * 4] = b4[cq];
        }
    }

    unsigned long long acc[8][4];
#pragma unroll
    for (int r = 0; r < 8; r++)
#pragma unroll
        for (int c = 0; c < 4; c++) acc[r][c] = 0ull;

    for (int kt = 0; kt < IN_FT; kt += 16) {
        // Load seq tile: 128 rows x 16 k = 512 float4, 4 per thread.
#pragma unroll
        for (int i = 0; i < 4; i++) {
            int idx = t + i * GT;           // 0..511
            int r   = idx >> 2;             // row 0..127
            int kq  = idx & 3;              // float4 slot in k
            float4 v = make_float4(0.f, 0.f, 0.f, 0.f);
            if (row0 + r < NN)
                v = *(const float4*)&seq[(size_t)(row0 + r) * IN_FT + kt + kq * 4];
            float* p = &sA[r * SA_STRIDE + kq * 4];
            p[0] = v.x; p[1] = v.y; p[2] = v.z; p[3] = v.w;
        }
        // Load W tile transposed: W[o][kt+..] -> sB[k][o]. 256 float4, 2/thread.
#pragma unroll
        for (int i = 0; i < 2; i++) {
            int idx = t + i * GT;
            int o   = idx >> 2;             // 0..63
            int kq  = idx & 3;              // 0..3
            float4 v = *(const float4*)&W[o * IN_FT + kt + kq * 4];
            sB[(kq * 4 + 0) * SB_STRIDE + o] = v.x;
            sB[(kq * 4 + 1) * SB_STRIDE + o] = v.y;
            sB[(kq * 4 + 2) * SB_STRIDE + o] = v.z;
            sB[(kq * 4 + 3) * SB_STRIDE + o] = v.w;
        }
        __syncthreads();

#pragma unroll
        for (int kk = 0; kk < 16; kk++) {
            // 8 B columns for this k as 4 f32x2 pairs (two LDS.128, 4-way bcast).
            const float* bp = &sB[kk * SB_STRIDE + tx * 8];
            float4 blo = *(const float4*)bp;
            float4 bhi = *(const float4*)(bp + 4);
            unsigned long long b0 = pack2(blo.x, blo.y);
            unsigned long long b1 = pack2(blo.z, blo.w);
            unsigned long long b2 = pack2(bhi.x, bhi.y);
            unsigned long long b3 = pack2(bhi.z, bhi.w);

#pragma unroll
            for (int r = 0; r < 8; r++) {
                float a = sA[(ty * 8 + r) * SA_STRIDE + kk];  // 8-way bcast
                unsigned long long aa = pack2(a, a);
                ffma2(acc[r][0], aa, b0);
                ffma2(acc[r][1], aa, b1);
                ffma2(acc[r][2], aa, b2);
                ffma2(acc[r][3], aa, b3);
            }
        }
        __syncthreads();
    }

#pragma unroll
    for (int r = 0; r < 8; r++) {
        int row = row0 + ty * 8 + r;
        if (row < NN) {
            float4 v0, v1;
            unpack2(acc[r][0], v0.x, v0.y);
            unpack2(acc[r][1], v0.z, v0.w);
            unpack2(acc[r][2], v1.x, v1.y);
            unpack2(acc[r][3], v1.z, v1.w);
            float* p = &fts[(size_t)row * OUT_FT + tx * 8];
            *(float4*)p       = v0;
            *(float4*)(p + 4) = v1;
        }
    }
}

// ---------------------------------------------------------------------------
// Scatter: out[dst] += fts[src] * val, 16 threads/edge, RED.v4 (no return).
// ---------------------------------------------------------------------------
__global__ __launch_bounds__(256) void scatter_kernel(
    const float* __restrict__ fts,
    const int* __restrict__ esrc, const int* __restrict__ edst,
    const float* __restrict__ eval, float* __restrict__ out)
{
    long long gid = (long long)blockIdx.x * blockDim.x + threadIdx.x;
    int e    = (int)(gid >> 4);
    int part = (int)(gid & 15);
    if (e >= NE) return;

    int   s = __ldg(&esrc[e]);
    int   d = __ldg(&edst[e]);
    float v = __ldg(&eval[e]);

    float4 f = *(const float4*)&fts[(size_t)s * OUT_FT + part * 4];
    float* p = &out[(size_t)d * OUT_FT + part * 4];
    asm volatile("red.global.add.v4.f32 [%0], {%1, %2, %3, %4};"
                 :: "l"(p), "f"(f.x * v), "f"(f.y * v), "f"(f.z * v), "f"(f.w * v)
                 : "memory");
}

// ---------------------------------------------------------------------------
// PReLU (scalar alpha), float4-vectorized, in place.
// ---------------------------------------------------------------------------
__global__ __launch_bounds__(256) void prelu_kernel(
    float4* __restrict__ out, const float* __restrict__ alpha)
{
    int i = blockIdx.x * blockDim.x + threadIdx.x;
    if (i < NN * OUT_FT / 4) {
        float a = __ldg(&alpha[0]);
        float4 x = out[i];
        x.x = (x.x >= 0.0f) ? x.x : a * x.x;
        x.y = (x.y >= 0.0f) ? x.y : a * x.y;
        x.z = (x.z >= 0.0f) ? x.z : a * x.z;
        x.w = (x.w >= 0.0f) ? x.w : a * x.w;
        out[i] = x;
    }
}

extern "C" void kernel_launch(void* const* d_in, const int* in_sizes, int n_in,
                              void* d_out, int out_size)
{
    const float* seq   = (const float*)d_in[0];
    const float* W     = (const float*)d_in[1];
    const float* bias  = (const float*)d_in[2];
    const float* alpha = (const float*)d_in[3];
    const int*   esrc  = (const int*)d_in[4];
    const int*   edst  = (const int*)d_in[5];
    const float* eval  = (const float*)d_in[6];
    float* out = (float*)d_out;

    float* fts;
    cudaGetSymbolAddress((void**)&fts, g_fts);

    // 1) GEMM (FFMA2, 8x8 thread tile) + fused out = bias
    gemm_kernel<<<(NN + 127) / 128, GT>>>(seq, W, bias, fts, out);

    // 2) scatter-add over edges
    long long total = (long long)NE * 16;
    scatter_kernel<<<(unsigned)((total + 255) / 256), 256>>>(fts, esrc, edst, eval, out);

    // 3) PReLU in place (vectorized)
    prelu_kernel<<<(NN * OUT_FT / 4 + 255) / 256, 256>>>((float4*)out, alpha);
}